// round 5
// baseline (speedup 1.0000x reference)
#include <cuda_runtime.h>
#include <math.h>

#define BB 16
#define CC 256
#define HH 128
#define WW 128
#define HWp (HH*WW)          // 16384
#define HW4 (HWp/4)          // 4096

// Scratch (device globals — no allocations allowed)
__device__ float g_sf[BB*2*HWp];        // [B,2,H,W]  avg(ch0), max(ch1)
__device__ float g_h1[BB*HWp*16];       // pixel-major [B,HW,16]; ALSO reused as
                                        // reduce partial scratch (first 8MB) before conv1
__device__ float g_samp[BB*2*HWp];      // [B,2,H,W]
__device__ float g_w2eff[2*9*16];       // transposed [2][9][16] group-averaged w2
__device__ float g_b2eff[2];

// ---------------------------------------------------------------------------
// Kernel 1a: partial channel reduce. 4 splits x 64 channels. 262144 threads.
// Partials (sum,max float4 pairs) stored in g_h1 scratch.
// ---------------------------------------------------------------------------
__global__ void k_reduce_part(const float* __restrict__ x) {
    int idx = blockIdx.x * blockDim.x + threadIdx.x;   // 0..262143
    int p4 = idx & 4095;
    int b  = (idx >> 12) & 15;
    int sp = idx >> 16;                                 // 0..3
    const float4* xp = reinterpret_cast<const float4*>(x)
                     + (size_t)b * CC * HW4 + (size_t)sp * 64 * HW4 + p4;

    float4 s = make_float4(0.f, 0.f, 0.f, 0.f);
    float4 m = make_float4(-1e30f, -1e30f, -1e30f, -1e30f);
    #pragma unroll 8
    for (int c = 0; c < 64; ++c) {
        float4 v = __ldg(xp + (size_t)c * HW4);
        s.x += v.x; s.y += v.y; s.z += v.z; s.w += v.w;
        m.x = fmaxf(m.x, v.x); m.y = fmaxf(m.y, v.y);
        m.z = fmaxf(m.z, v.z); m.w = fmaxf(m.w, v.w);
    }
    float4* part = reinterpret_cast<float4*>(g_h1);
    size_t base = ((size_t)(sp * 16 + b) * 2) * HW4 + p4;
    part[base]       = s;
    part[base + HW4] = m;
}

// ---------------------------------------------------------------------------
// Kernel 1b: combine 4 partials -> g_sf (avg ch0, max ch1). 65536 threads.
// ---------------------------------------------------------------------------
__global__ void k_combine() {
    int idx = blockIdx.x * blockDim.x + threadIdx.x;   // 0..65535
    int b  = idx >> 12;
    int p4 = idx & 4095;
    const float4* part = reinterpret_cast<const float4*>(g_h1);

    float4 s = make_float4(0.f, 0.f, 0.f, 0.f);
    float4 m = make_float4(-1e30f, -1e30f, -1e30f, -1e30f);
    #pragma unroll
    for (int sp = 0; sp < 4; ++sp) {
        size_t base = ((size_t)(sp * 16 + b) * 2) * HW4 + p4;
        float4 ps = part[base];
        float4 pm = part[base + HW4];
        s.x += ps.x; s.y += ps.y; s.z += ps.z; s.w += ps.w;
        m.x = fmaxf(m.x, pm.x); m.y = fmaxf(m.y, pm.y);
        m.z = fmaxf(m.z, pm.z); m.w = fmaxf(m.w, pm.w);
    }
    const float inv = 1.0f / (float)CC;
    s.x *= inv; s.y *= inv; s.z *= inv; s.w *= inv;

    float4* o = reinterpret_cast<float4*>(g_sf);
    o[(size_t)b * 2 * HW4 + p4]       = s;
    o[(size_t)b * 2 * HW4 + HW4 + p4] = m;
}

// ---------------------------------------------------------------------------
// Kernel 2: average w2/b2 over 49-channel groups (conv linear => exact),
// stored TRANSPOSED as [d][wo][ic] for broadcast LDS in k_off_sample.
// ---------------------------------------------------------------------------
__global__ void k_w2eff(const float* __restrict__ w2, const float* __restrict__ b2) {
    int i = threadIdx.x;
    if (i < 288) {
        int d  = i / 144;
        int r  = i % 144;
        int wo = r / 16;
        int ic = r % 16;
        float s = 0.f;
        #pragma unroll 7
        for (int j = 0; j < 49; ++j)
            s += w2[(size_t)(d * 49 + j) * 144 + ic * 9 + wo];
        g_w2eff[i] = s * (1.0f / 49.0f);
    }
    if (i < 2) {
        float s = 0.f;
        #pragma unroll 7
        for (int j = 0; j < 49; ++j) s += b2[i * 49 + j];
        g_b2eff[i] = s * (1.0f / 49.0f);
    }
}

// ---------------------------------------------------------------------------
// Kernel 3: conv3x3 (2->16) + BN + ReLU. 1 px/thread, writes PIXEL-MAJOR h1.
// ---------------------------------------------------------------------------
__global__ void k_conv1(const float* __restrict__ w1,
                        const float* __restrict__ gamma, const float* __restrict__ beta,
                        const float* __restrict__ mean,  const float* __restrict__ var) {
    __shared__ float ws[288];
    __shared__ float sc[16], bi[16];
    int t = threadIdx.x;
    for (int i = t; i < 288; i += blockDim.x) ws[i] = w1[i];
    if (t < 16) {
        float s = gamma[t] * rsqrtf(var[t] + 1e-5f);
        sc[t] = s;
        bi[t] = beta[t] - mean[t] * s;
    }
    __syncthreads();

    int idx = blockIdx.x * blockDim.x + t;      // 0..262143
    int b   = idx >> 14;
    int rem = idx & 16383;
    int y = rem >> 7, x = rem & 127;

    const float* sfb = g_sf + (size_t)b * 2 * HWp;
    float v[18];
    #pragma unroll
    for (int ic = 0; ic < 2; ++ic)
        #pragma unroll
        for (int kh = 0; kh < 3; ++kh)
            #pragma unroll
            for (int kw = 0; kw < 3; ++kw) {
                int yy = y + kh - 1, xx = x + kw - 1;
                float val = 0.f;
                if (yy >= 0 && yy < HH && xx >= 0 && xx < WW)
                    val = sfb[ic * HWp + yy * WW + xx];
                v[ic * 9 + kh * 3 + kw] = val;
            }

    float o[16];
    #pragma unroll
    for (int oc = 0; oc < 16; ++oc) {
        float acc = 0.f;
        #pragma unroll
        for (int k = 0; k < 18; ++k) acc = fmaf(v[k], ws[oc * 18 + k], acc);
        o[oc] = fmaxf(fmaf(acc, sc[oc], bi[oc]), 0.f);
    }

    float4* hb = reinterpret_cast<float4*>(g_h1) + ((size_t)b * HWp + rem) * 4;
    hb[0] = make_float4(o[0],  o[1],  o[2],  o[3]);
    hb[1] = make_float4(o[4],  o[5],  o[6],  o[7]);
    hb[2] = make_float4(o[8],  o[9],  o[10], o[11]);
    hb[3] = make_float4(o[12], o[13], o[14], o[15]);
}

// ---------------------------------------------------------------------------
// Kernel 4: conv3x3 (16->2 eff) + bias, tanh*0.5, grid, bilinear sample.
// 1 px/thread; h1 pixel-major -> 4 float4 loads per neighbor pixel.
// ---------------------------------------------------------------------------
__global__ void k_off_sample() {
    __shared__ float ws[288];      // [d][wo][ic] transposed
    __shared__ float b2s[2];
    int t = threadIdx.x;
    for (int i = t; i < 288; i += blockDim.x) ws[i] = g_w2eff[i];
    if (t < 2) b2s[t] = g_b2eff[t];
    __syncthreads();

    int idx = blockIdx.x * blockDim.x + t;      // 0..262143
    int b   = idx >> 14;
    int rem = idx & 16383;
    int y = rem >> 7, x = rem & 127;

    const float4* hb = reinterpret_cast<const float4*>(g_h1) + (size_t)b * HWp * 4;
    float ax = b2s[0], ay = b2s[1];

    #pragma unroll
    for (int dy = 0; dy < 3; ++dy) {
        int yy = y + dy - 1;
        if (yy < 0 || yy >= HH) continue;
        #pragma unroll
        for (int dx = 0; dx < 3; ++dx) {
            int xx = x + dx - 1;
            if (xx < 0 || xx >= WW) continue;
            const float4* hp = hb + (size_t)(yy * WW + xx) * 4;
            float4 h0 = hp[0], h1v = hp[1], h2 = hp[2], h3 = hp[3];
            const float* wx = &ws[(dy * 3 + dx) * 16];
            const float* wy = wx + 144;
            ax = fmaf(h0.x, wx[0], ax);  ay = fmaf(h0.x, wy[0], ay);
            ax = fmaf(h0.y, wx[1], ax);  ay = fmaf(h0.y, wy[1], ay);
            ax = fmaf(h0.z, wx[2], ax);  ay = fmaf(h0.z, wy[2], ay);
            ax = fmaf(h0.w, wx[3], ax);  ay = fmaf(h0.w, wy[3], ay);
            ax = fmaf(h1v.x, wx[4], ax); ay = fmaf(h1v.x, wy[4], ay);
            ax = fmaf(h1v.y, wx[5], ax); ay = fmaf(h1v.y, wy[5], ay);
            ax = fmaf(h1v.z, wx[6], ax); ay = fmaf(h1v.z, wy[6], ay);
            ax = fmaf(h1v.w, wx[7], ax); ay = fmaf(h1v.w, wy[7], ay);
            ax = fmaf(h2.x, wx[8], ax);  ay = fmaf(h2.x, wy[8], ay);
            ax = fmaf(h2.y, wx[9], ax);  ay = fmaf(h2.y, wy[9], ay);
            ax = fmaf(h2.z, wx[10], ax); ay = fmaf(h2.z, wy[10], ay);
            ax = fmaf(h2.w, wx[11], ax); ay = fmaf(h2.w, wy[11], ay);
            ax = fmaf(h3.x, wx[12], ax); ay = fmaf(h3.x, wy[12], ay);
            ax = fmaf(h3.y, wx[13], ax); ay = fmaf(h3.y, wy[13], ay);
            ax = fmaf(h3.z, wx[14], ax); ay = fmaf(h3.z, wy[14], ay);
            ax = fmaf(h3.w, wx[15], ax); ay = fmaf(h3.w, wy[15], ay);
        }
    }

    float txo = tanhf(ax) * 0.5f;
    float tyo = tanhf(ay) * 0.5f;
    float gxv = fmaf((float)x, 2.0f / 127.0f, -1.0f) + txo;
    float gyv = fmaf((float)y, 2.0f / 127.0f, -1.0f) + tyo;
    gxv = fminf(fmaxf(gxv, -1.f), 1.f);
    gyv = fminf(fmaxf(gyv, -1.f), 1.f);

    float ixf = ((gxv + 1.0f) * (float)WW - 1.0f) * 0.5f;
    float iyf = ((gyv + 1.0f) * (float)HH - 1.0f) * 0.5f;
    float x0f = floorf(ixf), y0f = floorf(iyf);
    int x0 = (int)x0f, y0 = (int)y0f;
    int x1 = x0 + 1,   y1 = y0 + 1;
    float wx1 = ixf - x0f, wx0 = 1.0f - wx1;
    float wy1 = iyf - y0f, wy0 = 1.0f - wy1;

    const float* s0 = g_sf + (size_t)b * 2 * HWp;  // avg
    const float* s1 = s0 + HWp;                    // max

    float w00 = wx0 * wy0, w10 = wx1 * wy0, w01 = wx0 * wy1, w11 = wx1 * wy1;
    bool vx0 = (x0 >= 0) & (x0 < WW), vx1 = (x1 >= 0) & (x1 < WW);
    bool vy0 = (y0 >= 0) & (y0 < HH), vy1 = (y1 >= 0) & (y1 < HH);

    float o0 = 0.f, o1 = 0.f;
    if (vy0 & vx0) { int p = y0 * WW + x0; o0 = fmaf(s0[p], w00, o0); o1 = fmaf(s1[p], w00, o1); }
    if (vy0 & vx1) { int p = y0 * WW + x1; o0 = fmaf(s0[p], w10, o0); o1 = fmaf(s1[p], w10, o1); }
    if (vy1 & vx0) { int p = y1 * WW + x0; o0 = fmaf(s0[p], w01, o0); o1 = fmaf(s1[p], w01, o1); }
    if (vy1 & vx1) { int p = y1 * WW + x1; o0 = fmaf(s0[p], w11, o0); o1 = fmaf(s1[p], w11, o1); }

    g_samp[(size_t)b * 2 * HWp + rem]       = o0;
    g_samp[(size_t)b * 2 * HWp + HWp + rem] = o1;
}

// ---------------------------------------------------------------------------
// Kernel 5: conv7x7 (2->1, pad 3) + sigmoid. 4 px/thread (aligned float4).
// ---------------------------------------------------------------------------
__global__ void k_attn(const float* __restrict__ aw, float* __restrict__ out) {
    __shared__ float ws[98];
    int t = threadIdx.x;
    if (t < 98) ws[t] = aw[t];
    __syncthreads();

    int idx = blockIdx.x * blockDim.x + t;      // 0..65535
    int b   = idx >> 12;
    int p4  = idx & 4095;
    int y   = p4 >> 5;
    int x4  = (p4 & 31) * 4;

    const float* sb = g_samp + (size_t)b * 2 * HWp;
    float acc[4] = {0.f, 0.f, 0.f, 0.f};

    #pragma unroll
    for (int ch = 0; ch < 2; ++ch)
        #pragma unroll
        for (int dy = 0; dy < 7; ++dy) {
            int yy = y + dy - 3;
            if (yy < 0 || yy >= HH) continue;
            const float* base = sb + ch * HWp + yy * WW + x4;
            float4 mv = *reinterpret_cast<const float4*>(base);
            float cl[10];
            if (x4 > 0) {
                float4 lv = *reinterpret_cast<const float4*>(base - 4);
                cl[0] = lv.y; cl[1] = lv.z; cl[2] = lv.w;
            } else {
                cl[0] = cl[1] = cl[2] = 0.f;
            }
            cl[3] = mv.x; cl[4] = mv.y; cl[5] = mv.z; cl[6] = mv.w;
            if (x4 < 124) {
                float4 rv = *reinterpret_cast<const float4*>(base + 4);
                cl[7] = rv.x; cl[8] = rv.y; cl[9] = rv.z;
            } else {
                cl[7] = cl[8] = cl[9] = 0.f;
            }
            #pragma unroll
            for (int kw = 0; kw < 7; ++kw) {
                float w = ws[ch * 49 + dy * 7 + kw];
                #pragma unroll
                for (int j = 0; j < 4; ++j)
                    acc[j] = fmaf(cl[kw + j], w, acc[j]);
            }
        }

    float4 o;
    o.x = 1.0f / (1.0f + expf(-acc[0]));
    o.y = 1.0f / (1.0f + expf(-acc[1]));
    o.z = 1.0f / (1.0f + expf(-acc[2]));
    o.w = 1.0f / (1.0f + expf(-acc[3]));
    *reinterpret_cast<float4*>(out + (size_t)b * HWp + y * WW + x4) = o;
}

// ---------------------------------------------------------------------------
extern "C" void kernel_launch(void* const* d_in, const int* in_sizes, int n_in,
                              void* d_out, int out_size) {
    const float* x     = (const float*)d_in[0];
    const float* w1    = (const float*)d_in[1];
    const float* gamma = (const float*)d_in[2];
    const float* beta  = (const float*)d_in[3];
    const float* mean  = (const float*)d_in[4];
    const float* var   = (const float*)d_in[5];
    const float* w2    = (const float*)d_in[6];
    const float* b2    = (const float*)d_in[7];
    const float* aw    = (const float*)d_in[8];
    float* out = (float*)d_out;

    k_reduce_part<<<1024, 256>>>(x);
    k_w2eff<<<1, 512>>>(w2, b2);
    k_combine<<<256, 256>>>();
    k_conv1<<<1024, 256>>>(w1, gamma, beta, mean, var);
    k_off_sample<<<1024, 256>>>();
    k_attn<<<256, 256>>>(aw, out);
}